// round 16
// baseline (speedup 1.0000x reference)
#include <cuda_runtime.h>
#include <cuda_fp16.h>
#include <cstdint>
#include <cstddef>

#define MAX_N 131072
#define MAX_E 2000000
#define OUTF 64
#define INF 128
#define BLK_M 128   // nodes per gemm block
#define KSTG 32     // K per stage

// Scratch (allocation-free rule: __device__ globals).
__device__ __align__(16) __half g_msg_h[(size_t)MAX_N * OUTF];   // fp16 messages
__device__ __align__(16) float g_alpha_src[MAX_N];
__device__ __align__(16) float g_alpha_dst[MAX_N];
__device__ __align__(16) int g_srt[MAX_E];         // src ids in dst-sorted order
__device__ __align__(16) int g_hist[MAX_N];        // zeroed by scan1 after use
__device__ __align__(16) int g_start[MAX_N];
__device__ __align__(16) int g_cursor[MAX_N];
__device__ __align__(16) int g_bsum[512];
__device__ int g_counter;   // last-block detector (reset by the last block)

static __device__ __forceinline__ unsigned h2_bits(__half2 h) {
    return *reinterpret_cast<unsigned*>(&h);
}
static __device__ __forceinline__ uint32_t f2tf32(float f) {
    uint32_t u;
    asm("cvt.rna.tf32.f32 %0, %1;" : "=r"(u) : "f"(f));
    return u;
}
static __device__ __forceinline__ void mma_tf32(
    float& c0, float& c1, float& c2, float& c3,
    uint32_t a0, uint32_t a1, uint32_t a2, uint32_t a3,
    uint32_t b0, uint32_t b1) {
    asm volatile(
        "mma.sync.aligned.m16n8k8.row.col.f32.tf32.tf32.f32 "
        "{%0,%1,%2,%3}, {%4,%5,%6,%7}, {%8,%9}, {%0,%1,%2,%3};"
        : "+f"(c0), "+f"(c1), "+f"(c2), "+f"(c3)
        : "r"(a0), "r"(a1), "r"(a2), "r"(a3), "r"(b0), "r"(b1));
}
// leaky_relu(e) == fmaxf(e, 0.01f*e) for all e (exact both signs)
static __device__ __forceinline__ float leaky(float e) {
    return fmaxf(e, 0.01f * e);
}

// ---------------------------------------------------------------------------
// Fused: dst histogram (slice) + messages = x@W^T via tf32 mma (fp16 out)
//        + EXACT fp32 alpha (v = W^T a computed fp32 from smem; alpha = x.v).
// ---------------------------------------------------------------------------
__global__ __launch_bounds__(256) void gemm_mma_kernel(
    const float* __restrict__ x, const float* __restrict__ W,
    const float* __restrict__ a, int N,
    const void* __restrict__ ei_raw, long long E, int epb) {
    __shared__ __align__(16) float As[BLK_M][KSTG + 4];
    __shared__ __align__(16) float Bs[OUTF][KSTG + 4];
    __shared__ __align__(16) float Avec[2 * OUTF];
    __shared__ __align__(16) float Vd[KSTG], Vs[KSTG];

    int tid = threadIdx.x;
    int warp = tid >> 5;
    int lane = tid & 31;
    int gid = lane >> 2;
    int tig = lane & 3;
    int nodeBase = blockIdx.x * BLK_M;

    {
        const int* ei32 = (const int*)ei_raw;
        bool is64 = (ei32[1] == 0) & (ei32[3] == 0) & (ei32[5] == 0) & (ei32[7] == 0);
        long long e0 = (long long)blockIdx.x * epb;
        long long e1 = e0 + epb; if (e1 > E) e1 = E;
        for (long long i = e0 + tid; i < e1; i += 256) {
            int d = is64 ? (int)__ldg(((const long long*)ei_raw) + E + i)
                         : __ldg(((const int*)ei_raw) + E + i);
            atomicAdd(&g_hist[d], 1);
        }
    }

    if (tid < 2 * OUTF) Avec[tid] = a[tid];

    float c[8][4];
#pragma unroll
    for (int nt = 0; nt < 8; nt++)
#pragma unroll
        for (int j = 0; j < 4; j++) c[nt][j] = 0.f;

    float alpha_d = 0.f, alpha_s = 0.f;

    for (int s = 0; s < 4; s++) {
        int k0 = s * KSTG;
        __syncthreads();
        for (int i = tid; i < BLK_M * KSTG; i += 256) {
            int r = i >> 5, k = i & 31;
            int gn = nodeBase + r; if (gn > N - 1) gn = N - 1;
            As[r][k] = x[(size_t)gn * INF + k0 + k];
        }
        for (int i = tid; i < OUTF * KSTG; i += 256) {
            int n = i >> 5, k = i & 31;
            Bs[n][k] = W[n * INF + k0 + k];
        }
        __syncthreads();
        if (tid < 64) {
            int k = tid & 31;
            bool dsel = tid < 32;
            float v = 0.f;
            const float* av = dsel ? Avec : (Avec + OUTF);
#pragma unroll 8
            for (int n = 0; n < OUTF; n++) v += Bs[n][k] * av[n];
            if (dsel) Vd[k] = v; else Vs[k] = v;
        }
        __syncthreads();
        int rbase = warp * 16;
#pragma unroll
        for (int ks = 0; ks < 4; ks++) {
            int kk = ks * 8;
            uint32_t A0 = f2tf32(As[rbase + gid][kk + tig]);
            uint32_t A1 = f2tf32(As[rbase + gid + 8][kk + tig]);
            uint32_t A2 = f2tf32(As[rbase + gid][kk + tig + 4]);
            uint32_t A3 = f2tf32(As[rbase + gid + 8][kk + tig + 4]);
#pragma unroll
            for (int nt = 0; nt < 8; nt++) {
                uint32_t B0 = f2tf32(Bs[nt * 8 + gid][kk + tig]);
                uint32_t B1 = f2tf32(Bs[nt * 8 + gid][kk + tig + 4]);
                mma_tf32(c[nt][0], c[nt][1], c[nt][2], c[nt][3],
                         A0, A1, A2, A3, B0, B1);
            }
        }
        if (tid < 128) {
            const float4* xr = reinterpret_cast<const float4*>(&As[tid][0]);
#pragma unroll
            for (int q = 0; q < KSTG / 4; q++) {
                float4 xv = xr[q];
                alpha_d += xv.x * Vd[4 * q] + xv.y * Vd[4 * q + 1]
                         + xv.z * Vd[4 * q + 2] + xv.w * Vd[4 * q + 3];
                alpha_s += xv.x * Vs[4 * q] + xv.y * Vs[4 * q + 1]
                         + xv.z * Vs[4 * q + 2] + xv.w * Vs[4 * q + 3];
            }
        }
    }

    int r0 = warp * 16 + gid;
    int cbase = 2 * tig;
#pragma unroll
    for (int nt = 0; nt < 8; nt++) {
        int col = nt * 8 + cbase;
        if (nodeBase + r0 < N) {
            __half2 h = __floats2half2_rn(c[nt][0], c[nt][1]);
            *reinterpret_cast<unsigned*>(
                g_msg_h + (size_t)(nodeBase + r0) * OUTF + col) = h2_bits(h);
        }
        if (nodeBase + r0 + 8 < N) {
            __half2 h = __floats2half2_rn(c[nt][2], c[nt][3]);
            *reinterpret_cast<unsigned*>(
                g_msg_h + (size_t)(nodeBase + r0 + 8) * OUTF + col) = h2_bits(h);
        }
    }
    if (tid < 128 && nodeBase + tid < N) {
        g_alpha_dst[nodeBase + tid] = alpha_d;
        g_alpha_src[nodeBase + tid] = alpha_s;
    }
}

// ---------------------------------------------------------------------------
// Scan stage 1 (+ fused stage 2): per-chunk exclusive scan into g_start;
// LAST arriving block scans the <=128 block totals and resets the counter.
// Also re-zeroes g_hist.
// ---------------------------------------------------------------------------
__global__ __launch_bounds__(256) void scan1_kernel(int N) {
    __shared__ int sh[256];
    __shared__ int s_last;
    int tid = threadIdx.x;
    int bid = blockIdx.x;
    int nblk = gridDim.x;

    int base = bid * 1024 + tid * 4;
    int v0 = (base + 0 < N) ? g_hist[base + 0] : 0;
    int v1 = (base + 1 < N) ? g_hist[base + 1] : 0;
    int v2 = (base + 2 < N) ? g_hist[base + 2] : 0;
    int v3 = (base + 3 < N) ? g_hist[base + 3] : 0;
    if (base + 0 < N) g_hist[base + 0] = 0;
    if (base + 1 < N) g_hist[base + 1] = 0;
    if (base + 2 < N) g_hist[base + 2] = 0;
    if (base + 3 < N) g_hist[base + 3] = 0;
    int t = v0 + v1 + v2 + v3;
    sh[tid] = t;
    __syncthreads();
    for (int off = 1; off < 256; off <<= 1) {
        int x = 0;
        if (tid >= off) x = sh[tid - off];
        __syncthreads();
        if (tid >= off) sh[tid] += x;
        __syncthreads();
    }
    int run = sh[tid] - t;
    if (base + 0 < N) g_start[base + 0] = run; run += v0;
    if (base + 1 < N) g_start[base + 1] = run; run += v1;
    if (base + 2 < N) g_start[base + 2] = run; run += v2;
    if (base + 3 < N) g_start[base + 3] = run;
    if (tid == 255) *(volatile int*)&g_bsum[bid] = sh[255];

    __threadfence();
    __syncthreads();
    if (tid == 0) s_last = (atomicAdd(&g_counter, 1) == nblk - 1);
    __syncthreads();
    if (s_last) {
        __threadfence();
        int v = (tid < nblk) ? *(volatile int*)&g_bsum[tid] : 0;
        sh[tid] = v;
        __syncthreads();
        for (int off = 1; off < 256; off <<= 1) {
            int x = 0;
            if (tid >= off) x = sh[tid - off];
            __syncthreads();
            if (tid >= off) sh[tid] += x;
            __syncthreads();
        }
        if (tid < nblk) g_bsum[tid] = sh[tid] - v;
        __syncthreads();
        if (tid == 0) g_counter = 0;
    }
}

__global__ void scan3_kernel(int N) {
    int i = blockIdx.x * blockDim.x + threadIdx.x;
    if (i < N) {
        int v = g_start[i] + g_bsum[i >> 10];
        g_start[i] = v;
        g_cursor[i] = v;
    }
}

// ---------------------------------------------------------------------------
// Place only: read (s,d), ticket-atomic, write 4B src record. No alpha
// gathers, no exp (moved to aggregate). 2 edges per thread.
// ---------------------------------------------------------------------------
__global__ void place_kernel(const void* __restrict__ ei_raw, long long E) {
    const int* ei32 = (const int*)ei_raw;
    bool is64 = (ei32[1] == 0) & (ei32[3] == 0) & (ei32[5] == 0) & (ei32[7] == 0);

    long long half = (E + 1) / 2;
    long long i0 = (long long)blockIdx.x * blockDim.x + threadIdx.x;
    if (i0 >= half) return;
    long long i1 = i0 + half;
    bool v1 = i1 < E;

    int s0, d0, s1 = 0, d1 = 0;
    if (is64) {
        const long long* e64 = (const long long*)ei_raw;
        s0 = (int)__ldg(e64 + i0);
        d0 = (int)__ldg(e64 + E + i0);
        if (v1) { s1 = (int)__ldg(e64 + i1); d1 = (int)__ldg(e64 + E + i1); }
    } else {
        s0 = __ldg(ei32 + i0);
        d0 = __ldg(ei32 + E + i0);
        if (v1) { s1 = __ldg(ei32 + i1); d1 = __ldg(ei32 + E + i1); }
    }
    int p0 = atomicAdd(&g_cursor[d0], 1);
    g_srt[p0] = s0;
    if (v1) {
        int p1 = atomicAdd(&g_cursor[d1], 1);
        g_srt[p1] = s1;
    }
}

// ---------------------------------------------------------------------------
// Aggregate: one warp per dst, 4 records/iter. Computes w inline:
// w = expf(leaky(alpha_dst[d] + alpha_src[s])), alpha_dst warp-uniform.
// Lane covers 2 cols; denom identical across lanes. Self-loop folded.
// ---------------------------------------------------------------------------
__global__ __launch_bounds__(256) void aggregate_kernel(float* __restrict__ out, int N) {
    int gw = (blockIdx.x * blockDim.x + threadIdx.x) >> 5;
    int lane = threadIdx.x & 31;
    if (gw >= N) return;
    int d = gw;
    int start = __ldg(&g_start[d]);
    int end = __ldg(&g_cursor[d]);

    float ad = __ldg(&g_alpha_dst[d]);
    float as_self = __ldg(&g_alpha_src[d]);
    __half2 hm = __ldg(reinterpret_cast<const __half2*>(
        g_msg_h + (size_t)d * OUTF) + lane);

    float accx = 0.f, accy = 0.f, denom = 0.f;
    int e = start;
    for (; e + 4 <= end; e += 4) {
        int s0 = __ldg(&g_srt[e]);
        int s1 = __ldg(&g_srt[e + 1]);
        int s2 = __ldg(&g_srt[e + 2]);
        int s3 = __ldg(&g_srt[e + 3]);
        // independent: 4 alpha gathers + 4 row gathers in flight
        float a0 = __ldg(&g_alpha_src[s0]);
        float a1 = __ldg(&g_alpha_src[s1]);
        float a2 = __ldg(&g_alpha_src[s2]);
        float a3 = __ldg(&g_alpha_src[s3]);
        __half2 h0 = __ldg(reinterpret_cast<const __half2*>(
            g_msg_h + (size_t)s0 * OUTF) + lane);
        __half2 h1 = __ldg(reinterpret_cast<const __half2*>(
            g_msg_h + (size_t)s1 * OUTF) + lane);
        __half2 h2 = __ldg(reinterpret_cast<const __half2*>(
            g_msg_h + (size_t)s2 * OUTF) + lane);
        __half2 h3 = __ldg(reinterpret_cast<const __half2*>(
            g_msg_h + (size_t)s3 * OUTF) + lane);
        float w0 = __expf(leaky(ad + a0));
        float w1 = __expf(leaky(ad + a1));
        float w2 = __expf(leaky(ad + a2));
        float w3 = __expf(leaky(ad + a3));
        float2 f0 = __half22float2(h0);
        float2 f1 = __half22float2(h1);
        float2 f2 = __half22float2(h2);
        float2 f3 = __half22float2(h3);
        accx += w0 * f0.x + w1 * f1.x + w2 * f2.x + w3 * f3.x;
        accy += w0 * f0.y + w1 * f1.y + w2 * f2.y + w3 * f3.y;
        denom += w0 + w1 + w2 + w3;
    }
    for (; e < end; e++) {
        int s = __ldg(&g_srt[e]);
        float as = __ldg(&g_alpha_src[s]);
        __half2 h = __ldg(reinterpret_cast<const __half2*>(
            g_msg_h + (size_t)s * OUTF) + lane);
        float w = __expf(leaky(ad + as));
        float2 f = __half22float2(h);
        accx += w * f.x;
        accy += w * f.y;
        denom += w;
    }

    // self-loop
    float ws = __expf(leaky(ad + as_self));
    float2 fm = __half22float2(hm);
    accx += ws * fm.x;
    accy += ws * fm.y;
    denom += ws;

    float inv = 1.0f / fmaxf(denom, 1e-6f);
    reinterpret_cast<float2*>(out + (size_t)d * OUTF)[lane] =
        make_float2(accx * inv, accy * inv);
}

extern "C" void kernel_launch(void* const* d_in, const int* in_sizes, int n_in,
                              void* d_out, int out_size) {
    // Identify inputs BY SIZE:
    //   a -> 128, W -> 8192, x -> N*128 (== 2*out_size), edge_index -> rest
    const float* x = nullptr;
    const float* W = nullptr;
    const float* a = nullptr;
    const void* ei = nullptr;
    long long ei_elems = 0;

    int N = out_size / OUTF;
    long long x_elems = (long long)N * INF;

    for (int i = 0; i < n_in; i++) {
        long long sz = in_sizes[i];
        if (sz == 2 * OUTF) {
            a = (const float*)d_in[i];
        } else if (sz == (long long)OUTF * INF) {
            W = (const float*)d_in[i];
        } else if (sz == x_elems) {
            x = (const float*)d_in[i];
        } else {
            ei = d_in[i];
            ei_elems = sz;
        }
    }
    float* out = (float*)d_out;
    long long E = ei_elems / 2;
    if (E > MAX_E) E = MAX_E;

    int grid = (N + BLK_M - 1) / BLK_M;
    int epb = (int)((E + grid - 1) / grid);
    gemm_mma_kernel<<<grid, 256>>>(x, W, a, N, ei, E, epb);

    int nblk = (N + 1023) / 1024;   // <= 128 blocks
    scan1_kernel<<<nblk, 256>>>(N);
    scan3_kernel<<<(N + 255) / 256, 256>>>(N);

    long long half = (E + 1) / 2;
    place_kernel<<<(unsigned int)((half + 255) / 256), 256>>>(ei, E);

    aggregate_kernel<<<(N * 32 + 255) / 256, 256>>>(out, N);
}

// round 17
// speedup vs baseline: 1.0457x; 1.0457x over previous
#include <cuda_runtime.h>
#include <cuda_fp16.h>
#include <cstdint>
#include <cstddef>

#define MAX_N 131072
#define MAX_E 2000000
#define OUTF 64
#define INF 128
#define BLK_M 128   // nodes per gemm block
#define KSTG 32     // K per stage

// Scratch (allocation-free rule: __device__ globals).
__device__ __align__(16) __half g_msg_h[(size_t)MAX_N * OUTF];   // fp16 messages
__device__ __align__(16) float g_alpha_src[MAX_N];
__device__ __align__(16) float g_alpha_dst[MAX_N];
__device__ __align__(16) float2 g_sorted[MAX_E];   // (w, s-bits) dst-sorted
__device__ __align__(16) int g_hist[MAX_N];        // zeroed by scan1 after use
__device__ __align__(16) int g_start[MAX_N];       // BLOCK-RELATIVE exclusive scan
__device__ __align__(16) int g_cursor[MAX_N];      // same, mutated by place
__device__ __align__(16) int g_bsum[512];          // per-1024-chunk global offsets
__device__ int g_counter;   // last-block detector (reset by the last block)

static __device__ __forceinline__ unsigned h2_bits(__half2 h) {
    return *reinterpret_cast<unsigned*>(&h);
}
static __device__ __forceinline__ uint32_t f2tf32(float f) {
    uint32_t u;
    asm("cvt.rna.tf32.f32 %0, %1;" : "=r"(u) : "f"(f));
    return u;
}
static __device__ __forceinline__ void mma_tf32(
    float& c0, float& c1, float& c2, float& c3,
    uint32_t a0, uint32_t a1, uint32_t a2, uint32_t a3,
    uint32_t b0, uint32_t b1) {
    asm volatile(
        "mma.sync.aligned.m16n8k8.row.col.f32.tf32.tf32.f32 "
        "{%0,%1,%2,%3}, {%4,%5,%6,%7}, {%8,%9}, {%0,%1,%2,%3};"
        : "+f"(c0), "+f"(c1), "+f"(c2), "+f"(c3)
        : "r"(a0), "r"(a1), "r"(a2), "r"(a3), "r"(b0), "r"(b1));
}

// ---------------------------------------------------------------------------
// Fused: dst histogram (slice) + messages = x@W^T via tf32 mma (fp16 out)
//        + EXACT fp32 alpha (v = W^T a computed fp32 from smem; alpha = x.v).
// ---------------------------------------------------------------------------
__global__ __launch_bounds__(256) void gemm_mma_kernel(
    const float* __restrict__ x, const float* __restrict__ W,
    const float* __restrict__ a, int N,
    const void* __restrict__ ei_raw, long long E, int epb) {
    __shared__ __align__(16) float As[BLK_M][KSTG + 4];
    __shared__ __align__(16) float Bs[OUTF][KSTG + 4];
    __shared__ __align__(16) float Avec[2 * OUTF];
    __shared__ __align__(16) float Vd[KSTG], Vs[KSTG];

    int tid = threadIdx.x;
    int warp = tid >> 5;
    int lane = tid & 31;
    int gid = lane >> 2;
    int tig = lane & 3;
    int nodeBase = blockIdx.x * BLK_M;

    {
        const int* ei32 = (const int*)ei_raw;
        bool is64 = (ei32[1] == 0) & (ei32[3] == 0) & (ei32[5] == 0) & (ei32[7] == 0);
        long long e0 = (long long)blockIdx.x * epb;
        long long e1 = e0 + epb; if (e1 > E) e1 = E;
        for (long long i = e0 + tid; i < e1; i += 256) {
            int d = is64 ? (int)__ldg(((const long long*)ei_raw) + E + i)
                         : __ldg(((const int*)ei_raw) + E + i);
            atomicAdd(&g_hist[d], 1);
        }
    }

    if (tid < 2 * OUTF) Avec[tid] = a[tid];

    float c[8][4];
#pragma unroll
    for (int nt = 0; nt < 8; nt++)
#pragma unroll
        for (int j = 0; j < 4; j++) c[nt][j] = 0.f;

    float alpha_d = 0.f, alpha_s = 0.f;

    for (int s = 0; s < 4; s++) {
        int k0 = s * KSTG;
        __syncthreads();
        for (int i = tid; i < BLK_M * KSTG; i += 256) {
            int r = i >> 5, k = i & 31;
            int gn = nodeBase + r; if (gn > N - 1) gn = N - 1;
            As[r][k] = x[(size_t)gn * INF + k0 + k];
        }
        for (int i = tid; i < OUTF * KSTG; i += 256) {
            int n = i >> 5, k = i & 31;
            Bs[n][k] = W[n * INF + k0 + k];
        }
        __syncthreads();
        if (tid < 64) {
            int k = tid & 31;
            bool dsel = tid < 32;
            float v = 0.f;
            const float* av = dsel ? Avec : (Avec + OUTF);
#pragma unroll 8
            for (int n = 0; n < OUTF; n++) v += Bs[n][k] * av[n];
            if (dsel) Vd[k] = v; else Vs[k] = v;
        }
        __syncthreads();
        int rbase = warp * 16;
#pragma unroll
        for (int ks = 0; ks < 4; ks++) {
            int kk = ks * 8;
            uint32_t A0 = f2tf32(As[rbase + gid][kk + tig]);
            uint32_t A1 = f2tf32(As[rbase + gid + 8][kk + tig]);
            uint32_t A2 = f2tf32(As[rbase + gid][kk + tig + 4]);
            uint32_t A3 = f2tf32(As[rbase + gid + 8][kk + tig + 4]);
#pragma unroll
            for (int nt = 0; nt < 8; nt++) {
                uint32_t B0 = f2tf32(Bs[nt * 8 + gid][kk + tig]);
                uint32_t B1 = f2tf32(Bs[nt * 8 + gid][kk + tig + 4]);
                mma_tf32(c[nt][0], c[nt][1], c[nt][2], c[nt][3],
                         A0, A1, A2, A3, B0, B1);
            }
        }
        if (tid < 128) {
            const float4* xr = reinterpret_cast<const float4*>(&As[tid][0]);
#pragma unroll
            for (int q = 0; q < KSTG / 4; q++) {
                float4 xv = xr[q];
                alpha_d += xv.x * Vd[4 * q] + xv.y * Vd[4 * q + 1]
                         + xv.z * Vd[4 * q + 2] + xv.w * Vd[4 * q + 3];
                alpha_s += xv.x * Vs[4 * q] + xv.y * Vs[4 * q + 1]
                         + xv.z * Vs[4 * q + 2] + xv.w * Vs[4 * q + 3];
            }
        }
    }

    int r0 = warp * 16 + gid;
    int cbase = 2 * tig;
#pragma unroll
    for (int nt = 0; nt < 8; nt++) {
        int col = nt * 8 + cbase;
        if (nodeBase + r0 < N) {
            __half2 h = __floats2half2_rn(c[nt][0], c[nt][1]);
            *reinterpret_cast<unsigned*>(
                g_msg_h + (size_t)(nodeBase + r0) * OUTF + col) = h2_bits(h);
        }
        if (nodeBase + r0 + 8 < N) {
            __half2 h = __floats2half2_rn(c[nt][2], c[nt][3]);
            *reinterpret_cast<unsigned*>(
                g_msg_h + (size_t)(nodeBase + r0 + 8) * OUTF + col) = h2_bits(h);
        }
    }
    if (tid < 128 && nodeBase + tid < N) {
        g_alpha_dst[nodeBase + tid] = alpha_d;
        g_alpha_src[nodeBase + tid] = alpha_s;
    }
}

// ---------------------------------------------------------------------------
// Scan (fused stages 1+2, stage 3 ELIMINATED): per-chunk exclusive scan into
// g_start AND g_cursor (block-relative); chunk totals to g_bsum; the LAST
// arriving block scans the <=128 totals (exclusive) and resets the counter.
// Consumers add g_bsum[d>>10] at use. Also re-zeroes g_hist.
// ---------------------------------------------------------------------------
__global__ __launch_bounds__(256) void scan1_kernel(int N) {
    __shared__ int sh[256];
    __shared__ int s_last;
    int tid = threadIdx.x;
    int bid = blockIdx.x;
    int nblk = gridDim.x;

    int base = bid * 1024 + tid * 4;
    int v0 = (base + 0 < N) ? g_hist[base + 0] : 0;
    int v1 = (base + 1 < N) ? g_hist[base + 1] : 0;
    int v2 = (base + 2 < N) ? g_hist[base + 2] : 0;
    int v3 = (base + 3 < N) ? g_hist[base + 3] : 0;
    if (base + 0 < N) g_hist[base + 0] = 0;
    if (base + 1 < N) g_hist[base + 1] = 0;
    if (base + 2 < N) g_hist[base + 2] = 0;
    if (base + 3 < N) g_hist[base + 3] = 0;
    int t = v0 + v1 + v2 + v3;
    sh[tid] = t;
    __syncthreads();
    for (int off = 1; off < 256; off <<= 1) {
        int x = 0;
        if (tid >= off) x = sh[tid - off];
        __syncthreads();
        if (tid >= off) sh[tid] += x;
        __syncthreads();
    }
    int run = sh[tid] - t;
    if (base + 0 < N) { g_start[base + 0] = run; g_cursor[base + 0] = run; } run += v0;
    if (base + 1 < N) { g_start[base + 1] = run; g_cursor[base + 1] = run; } run += v1;
    if (base + 2 < N) { g_start[base + 2] = run; g_cursor[base + 2] = run; } run += v2;
    if (base + 3 < N) { g_start[base + 3] = run; g_cursor[base + 3] = run; }
    if (tid == 255) *(volatile int*)&g_bsum[bid] = sh[255];

    __threadfence();
    __syncthreads();
    if (tid == 0) s_last = (atomicAdd(&g_counter, 1) == nblk - 1);
    __syncthreads();
    if (s_last) {
        __threadfence();
        int v = (tid < nblk) ? *(volatile int*)&g_bsum[tid] : 0;
        sh[tid] = v;
        __syncthreads();
        for (int off = 1; off < 256; off <<= 1) {
            int x = 0;
            if (tid >= off) x = sh[tid - off];
            __syncthreads();
            if (tid >= off) sh[tid] += x;
            __syncthreads();
        }
        if (tid < nblk) g_bsum[tid] = sh[tid] - v;   // exclusive chunk offsets
        __syncthreads();
        if (tid == 0) g_counter = 0;                 // reset for next replay
    }
}

// ---------------------------------------------------------------------------
// Weight + place: 2 edges per thread (range halves; both coalesced).
// pos = g_bsum[d>>10] (chunk offset) + block-relative ticket.
// ---------------------------------------------------------------------------
__global__ void weight_place_kernel(const void* __restrict__ ei_raw, long long E) {
    const int* ei32 = (const int*)ei_raw;
    bool is64 = (ei32[1] == 0) & (ei32[3] == 0) & (ei32[5] == 0) & (ei32[7] == 0);

    long long half = (E + 1) / 2;
    long long i0 = (long long)blockIdx.x * blockDim.x + threadIdx.x;
    if (i0 >= half) return;
    long long i1 = i0 + half;
    bool v1 = i1 < E;

    int s0, d0, s1 = 0, d1 = 0;
    if (is64) {
        const long long* e64 = (const long long*)ei_raw;
        s0 = (int)__ldg(e64 + i0);
        d0 = (int)__ldg(e64 + E + i0);
        if (v1) { s1 = (int)__ldg(e64 + i1); d1 = (int)__ldg(e64 + E + i1); }
    } else {
        s0 = __ldg(ei32 + i0);
        d0 = __ldg(ei32 + E + i0);
        if (v1) { s1 = __ldg(ei32 + i1); d1 = __ldg(ei32 + E + i1); }
    }
    float ad0 = g_alpha_dst[d0], as0 = g_alpha_src[s0];
    float ad1 = 0.f, as1 = 0.f;
    if (v1) { ad1 = g_alpha_dst[d1]; as1 = g_alpha_src[s1]; }

    float e0 = ad0 + as0;
    e0 = (e0 >= 0.f) ? e0 : 0.01f * e0;
    float w0 = __expf(e0);
    int p0 = __ldg(&g_bsum[d0 >> 10]) + atomicAdd(&g_cursor[d0], 1);
    g_sorted[p0] = make_float2(w0, __int_as_float(s0));
    if (v1) {
        float e1 = ad1 + as1;
        e1 = (e1 >= 0.f) ? e1 : 0.01f * e1;
        float w1 = __expf(e1);
        int p1 = __ldg(&g_bsum[d1 >> 10]) + atomicAdd(&g_cursor[d1], 1);
        g_sorted[p1] = make_float2(w1, __int_as_float(s1));
    }
}

// ---------------------------------------------------------------------------
// Aggregate: one warp per dst, 4 records/iter (plain R12 loop — measured
// best). start/end = block-relative + chunk offset. Self-loop folded.
// ---------------------------------------------------------------------------
__global__ __launch_bounds__(256) void aggregate_kernel(float* __restrict__ out, int N) {
    int gw = (blockIdx.x * blockDim.x + threadIdx.x) >> 5;
    int lane = threadIdx.x & 31;
    if (gw >= N) return;
    int d = gw;
    int boff = __ldg(&g_bsum[d >> 10]);
    int start = __ldg(&g_start[d]) + boff;
    int end = __ldg(&g_cursor[d]) + boff;

    // self-loop loads issued early (overlap with loop)
    float sl_ad = __ldg(&g_alpha_dst[d]);
    float sl_as = __ldg(&g_alpha_src[d]);
    __half2 hm = __ldg(reinterpret_cast<const __half2*>(
        g_msg_h + (size_t)d * OUTF) + lane);

    float accx = 0.f, accy = 0.f, denom = 0.f;
    int e = start;
    for (; e + 4 <= end; e += 4) {
        float2 r0 = __ldg(&g_sorted[e]);
        float2 r1 = __ldg(&g_sorted[e + 1]);
        float2 r2 = __ldg(&g_sorted[e + 2]);
        float2 r3 = __ldg(&g_sorted[e + 3]);
        __half2 h0 = __ldg(reinterpret_cast<const __half2*>(
            g_msg_h + (size_t)__float_as_int(r0.y) * OUTF) + lane);
        __half2 h1 = __ldg(reinterpret_cast<const __half2*>(
            g_msg_h + (size_t)__float_as_int(r1.y) * OUTF) + lane);
        __half2 h2 = __ldg(reinterpret_cast<const __half2*>(
            g_msg_h + (size_t)__float_as_int(r2.y) * OUTF) + lane);
        __half2 h3 = __ldg(reinterpret_cast<const __half2*>(
            g_msg_h + (size_t)__float_as_int(r3.y) * OUTF) + lane);
        float2 f0 = __half22float2(h0);
        float2 f1 = __half22float2(h1);
        float2 f2 = __half22float2(h2);
        float2 f3 = __half22float2(h3);
        accx += r0.x * f0.x + r1.x * f1.x + r2.x * f2.x + r3.x * f3.x;
        accy += r0.x * f0.y + r1.x * f1.y + r2.x * f2.y + r3.x * f3.y;
        denom += r0.x + r1.x + r2.x + r3.x;
    }
    for (; e < end; e++) {
        float2 r = __ldg(&g_sorted[e]);
        __half2 h = __ldg(reinterpret_cast<const __half2*>(
            g_msg_h + (size_t)__float_as_int(r.y) * OUTF) + lane);
        float2 f = __half22float2(h);
        accx += r.x * f.x;
        accy += r.x * f.y;
        denom += r.x;
    }

    float e0 = sl_ad + sl_as;
    e0 = (e0 >= 0.f) ? e0 : 0.01f * e0;
    float ws = __expf(e0);
    float2 fm = __half22float2(hm);
    accx += ws * fm.x;
    accy += ws * fm.y;
    denom += ws;

    float inv = 1.0f / fmaxf(denom, 1e-6f);
    reinterpret_cast<float2*>(out + (size_t)d * OUTF)[lane] =
        make_float2(accx * inv, accy * inv);
}

extern "C" void kernel_launch(void* const* d_in, const int* in_sizes, int n_in,
                              void* d_out, int out_size) {
    // Identify inputs BY SIZE:
    //   a -> 128, W -> 8192, x -> N*128 (== 2*out_size), edge_index -> rest
    const float* x = nullptr;
    const float* W = nullptr;
    const float* a = nullptr;
    const void* ei = nullptr;
    long long ei_elems = 0;

    int N = out_size / OUTF;
    long long x_elems = (long long)N * INF;

    for (int i = 0; i < n_in; i++) {
        long long sz = in_sizes[i];
        if (sz == 2 * OUTF) {
            a = (const float*)d_in[i];
        } else if (sz == (long long)OUTF * INF) {
            W = (const float*)d_in[i];
        } else if (sz == x_elems) {
            x = (const float*)d_in[i];
        } else {
            ei = d_in[i];
            ei_elems = sz;
        }
    }
    float* out = (float*)d_out;
    long long E = ei_elems / 2;
    if (E > MAX_E) E = MAX_E;

    int grid = (N + BLK_M - 1) / BLK_M;
    int epb = (int)((E + grid - 1) / grid);
    gemm_mma_kernel<<<grid, 256>>>(x, W, a, N, ei, E, epb);

    int nblk = (N + 1023) / 1024;   // <= 128 blocks
    scan1_kernel<<<nblk, 256>>>(N);

    long long half = (E + 1) / 2;
    weight_place_kernel<<<(unsigned int)((half + 255) / 256), 256>>>(ei, E);

    aggregate_kernel<<<(N * 32 + 255) / 256, 256>>>(out, N);
}